// round 2
// baseline (speedup 1.0000x reference)
#include <cuda_runtime.h>
#include <math.h>

#define D_MODEL  1024
#define N_HEADS  16
#define HEAD_DIM 64
#define BATCH    4
#define SEQ      2048
#define M_ROWS   (BATCH * SEQ)   // 8192

// ---------------- scratch (static device arrays; no allocation allowed) ----
__device__ float g_Q[BATCH * N_HEADS * SEQ * HEAD_DIM];   // [B,H,T,Dh]
__device__ float g_K[BATCH * N_HEADS * SEQ * HEAD_DIM];
__device__ float g_V[BATCH * N_HEADS * SEQ * HEAD_DIM];
__device__ float g_O[M_ROWS * D_MODEL];                   // [B,T,D] attn output

// ---------------- SGEMM: C = A[M,K] @ W[N,K]^T ----------------------------
// BM=BN=128, BK=8, 256 threads, 8x8 register tile per thread.
#define BM 128
#define BN 128
#define BK 8
#define TM 8
#define TN 8

__global__ void __launch_bounds__(256)
sgemm_kernel(const float* __restrict__ A,
             const float* __restrict__ W0,
             const float* __restrict__ W1,
             const float* __restrict__ W2,
             int mode,                      // 0: QKV->head layout, 1: plain out
             float* __restrict__ outPlain)
{
    __shared__ float As[BK][BM + 4];
    __shared__ float Bs[BK][BN + 4];

    const int K = D_MODEL;
    const int tid = threadIdx.x;
    const int tx = tid & 15;       // 0..15  (N dir)
    const int ty = tid >> 4;       // 0..15  (M dir)
    const int m0 = blockIdx.y * BM;
    const int n0 = blockIdx.x * BN;

    const float* W;
    float* dstQKV = nullptr;
    const float* Aptr;
    if (mode == 0) {
        Aptr = A;
        if (blockIdx.z == 0)      { W = W0; dstQKV = g_Q; }
        else if (blockIdx.z == 1) { W = W1; dstQKV = g_K; }
        else                      { W = W2; dstQKV = g_V; }
    } else {
        Aptr = g_O;
        W = W0;   // Wo
    }

    const int lr = tid >> 1;           // 0..127
    const int lc = (tid & 1) * 4;      // 0 or 4

    float acc[TM][TN];
#pragma unroll
    for (int i = 0; i < TM; i++)
#pragma unroll
        for (int j = 0; j < TN; j++) acc[i][j] = 0.0f;

    for (int k0 = 0; k0 < K; k0 += BK) {
        float4 av = *(const float4*)(Aptr + (size_t)(m0 + lr) * K + k0 + lc);
        float4 wv = *(const float4*)(W    + (size_t)(n0 + lr) * K + k0 + lc);
        As[lc + 0][lr] = av.x; As[lc + 1][lr] = av.y;
        As[lc + 2][lr] = av.z; As[lc + 3][lr] = av.w;
        Bs[lc + 0][lr] = wv.x; Bs[lc + 1][lr] = wv.y;
        Bs[lc + 2][lr] = wv.z; Bs[lc + 3][lr] = wv.w;
        __syncthreads();

#pragma unroll
        for (int k = 0; k < BK; k++) {
            float4 a0 = *(const float4*)&As[k][ty * TM];
            float4 a1 = *(const float4*)&As[k][ty * TM + 4];
            float4 b0 = *(const float4*)&Bs[k][tx * TN];
            float4 b1 = *(const float4*)&Bs[k][tx * TN + 4];
            float a[TM] = {a0.x, a0.y, a0.z, a0.w, a1.x, a1.y, a1.z, a1.w};
            float b[TN] = {b0.x, b0.y, b0.z, b0.w, b1.x, b1.y, b1.z, b1.w};
#pragma unroll
            for (int i = 0; i < TM; i++)
#pragma unroll
                for (int j = 0; j < TN; j++)
                    acc[i][j] += a[i] * b[j];
        }
        __syncthreads();
    }

    if (mode == 0) {
        const int n = n0 + tx * TN;
        const int h = n >> 6;
        const int d = n & 63;
#pragma unroll
        for (int i = 0; i < TM; i++) {
            int m = m0 + ty * TM + i;
            int b = m >> 11;          // /2048
            int t = m & 2047;
            float* dst = dstQKV +
                ((size_t)(b * N_HEADS + h) * SEQ + t) * HEAD_DIM + d;
            *(float4*)dst       = make_float4(acc[i][0], acc[i][1], acc[i][2], acc[i][3]);
            *(float4*)(dst + 4) = make_float4(acc[i][4], acc[i][5], acc[i][6], acc[i][7]);
        }
    } else {
#pragma unroll
        for (int i = 0; i < TM; i++) {
            int m = m0 + ty * TM + i;
            float* dst = outPlain + (size_t)m * D_MODEL + n0 + tx * TN;
            *(float4*)dst       = make_float4(acc[i][0], acc[i][1], acc[i][2], acc[i][3]);
            *(float4*)(dst + 4) = make_float4(acc[i][4], acc[i][5], acc[i][6], acc[i][7]);
        }
    }
}

// ---------------- RoPE (in-place on g_Q, g_K) ------------------------------
__global__ void __launch_bounds__(256)
rope_kernel()
{
    int idx = blockIdx.x * blockDim.x + threadIdx.x;   // B*H*T*32 = 4194304
    int d  = idx & 31;
    int t  = (idx >> 5) & (SEQ - 1);
    int bh = idx >> 16;                                // SEQ*32 = 65536

    // inv_freq = 10000^(-2d/64) = exp(-d * ln(10000)/32)
    float inv_freq = expf(-(float)d * 0.28782313662425573f);
    float ang = (float)t * inv_freq;
    float s, c;
    sincosf(ang, &s, &c);

    size_t base = ((size_t)bh * SEQ + t) * HEAD_DIM + d;
    float q1 = g_Q[base], q2 = g_Q[base + 32];
    g_Q[base]      = q1 * c - q2 * s;
    g_Q[base + 32] = q2 * c + q1 * s;
    float k1 = g_K[base], k2 = g_K[base + 32];
    g_K[base]      = k1 * c - k2 * s;
    g_K[base + 32] = k2 * c + k1 * s;
}

// ---------------- Flash attention (causal, fp32) ----------------------------
// 64 queries x 64 keys per tile; 128 threads; each thread owns 4 rows x 8 cols.
#define FA_LD 68   // padded row stride in smem

__global__ void __launch_bounds__(128)
flash_kernel()
{
    extern __shared__ float sm[];
    float* Qt = sm;                   // [64][68]  Qt[d][r]
    float* Kt = Qt + 64 * FA_LD;      // [64][68]  Kt[d][c]
    float* Vs = Kt + 64 * FA_LD;      // [64][68]  Vs[k][d]
    float* Ps = Vs + 64 * FA_LD;      // [64][68]  Ps[r][c]

    const int it = (int)gridDim.x - 1 - (int)blockIdx.x;  // heavy tiles first
    const int bh = blockIdx.y;
    const float* Qg = g_Q + (size_t)bh * SEQ * HEAD_DIM;
    const float* Kg = g_K + (size_t)bh * SEQ * HEAD_DIM;
    const float* Vg = g_V + (size_t)bh * SEQ * HEAD_DIM;

    const int tid = threadIdx.x;
    const int tx = tid & 7;    // col group (8 cols)
    const int ty = tid >> 3;   // row group (4 rows)

    // Load Q tile transposed: Qt[d][r] = Q[it*64+r][d]
#pragma unroll
    for (int p = 0; p < 8; p++) {
        int i  = tid + p * 128;        // 0..1023 (64 rows x 16 float4)
        int r  = i >> 4;
        int c4 = (i & 15) << 2;
        float4 v = *(const float4*)(Qg + (size_t)(it * 64 + r) * 64 + c4);
        Qt[(c4 + 0) * FA_LD + r] = v.x;
        Qt[(c4 + 1) * FA_LD + r] = v.y;
        Qt[(c4 + 2) * FA_LD + r] = v.z;
        Qt[(c4 + 3) * FA_LD + r] = v.w;
    }

    float o[4][8];
    float m_i[4], l_i[4];
#pragma unroll
    for (int i = 0; i < 4; i++) {
        m_i[i] = -INFINITY; l_i[i] = 0.0f;
#pragma unroll
        for (int j = 0; j < 8; j++) o[i][j] = 0.0f;
    }

    for (int jt = 0; jt <= it; jt++) {
        __syncthreads();   // previous iteration's reads of Kt/Vs/Ps done
        // Load K transposed + V straight
#pragma unroll
        for (int p = 0; p < 8; p++) {
            int i  = tid + p * 128;
            int r  = i >> 4;
            int c4 = (i & 15) << 2;
            float4 kv = *(const float4*)(Kg + (size_t)(jt * 64 + r) * 64 + c4);
            Kt[(c4 + 0) * FA_LD + r] = kv.x;
            Kt[(c4 + 1) * FA_LD + r] = kv.y;
            Kt[(c4 + 2) * FA_LD + r] = kv.z;
            Kt[(c4 + 3) * FA_LD + r] = kv.w;
            float4 vv = *(const float4*)(Vg + (size_t)(jt * 64 + r) * 64 + c4);
            *(float4*)(Vs + r * FA_LD + c4) = vv;
        }
        __syncthreads();

        // S = Q @ K^T
        float s[4][8];
#pragma unroll
        for (int i = 0; i < 4; i++)
#pragma unroll
            for (int j = 0; j < 8; j++) s[i][j] = 0.0f;

#pragma unroll 8
        for (int d = 0; d < 64; d++) {
            float4 aq = *(const float4*)(Qt + d * FA_LD + ty * 4);
            float4 b0 = *(const float4*)(Kt + d * FA_LD + tx * 8);
            float4 b1 = *(const float4*)(Kt + d * FA_LD + tx * 8 + 4);
            float a[4]  = {aq.x, aq.y, aq.z, aq.w};
            float bb[8] = {b0.x, b0.y, b0.z, b0.w, b1.x, b1.y, b1.z, b1.w};
#pragma unroll
            for (int i = 0; i < 4; i++)
#pragma unroll
                for (int j = 0; j < 8; j++)
                    s[i][j] += a[i] * bb[j];
        }

        // scale + causal mask (only the diagonal tile needs masking)
        if (jt == it) {
#pragma unroll
            for (int i = 0; i < 4; i++)
#pragma unroll
                for (int j = 0; j < 8; j++) {
                    if (tx * 8 + j > ty * 4 + i) s[i][j] = -INFINITY;
                    else                         s[i][j] *= 0.125f;
                }
        } else {
#pragma unroll
            for (int i = 0; i < 4; i++)
#pragma unroll
                for (int j = 0; j < 8; j++) s[i][j] *= 0.125f;
        }

        // online softmax update (row stats reduced over the 8 tx lanes)
#pragma unroll
        for (int i = 0; i < 4; i++) {
            float mt = s[i][0];
#pragma unroll
            for (int j = 1; j < 8; j++) mt = fmaxf(mt, s[i][j]);
            mt = fmaxf(mt, __shfl_xor_sync(0xffffffffu, mt, 1));
            mt = fmaxf(mt, __shfl_xor_sync(0xffffffffu, mt, 2));
            mt = fmaxf(mt, __shfl_xor_sync(0xffffffffu, mt, 4));

            float mn   = fmaxf(m_i[i], mt);
            float resc = __expf(m_i[i] - mn);
            m_i[i] = mn;

            float rs = 0.0f;
#pragma unroll
            for (int j = 0; j < 8; j++) {
                float p = __expf(s[i][j] - mn);
                s[i][j] = p;
                rs += p;
            }
            rs += __shfl_xor_sync(0xffffffffu, rs, 1);
            rs += __shfl_xor_sync(0xffffffffu, rs, 2);
            rs += __shfl_xor_sync(0xffffffffu, rs, 4);

            l_i[i] = l_i[i] * resc + rs;
#pragma unroll
            for (int j = 0; j < 8; j++) o[i][j] *= resc;
        }

        // stage P
#pragma unroll
        for (int i = 0; i < 4; i++) {
            float* pr = Ps + (ty * 4 + i) * FA_LD + tx * 8;
            *(float4*)pr       = make_float4(s[i][0], s[i][1], s[i][2], s[i][3]);
            *(float4*)(pr + 4) = make_float4(s[i][4], s[i][5], s[i][6], s[i][7]);
        }
        __syncthreads();

        // O += P @ V
#pragma unroll 8
        for (int k = 0; k < 64; k++) {
            float a[4];
#pragma unroll
            for (int i = 0; i < 4; i++) a[i] = Ps[(ty * 4 + i) * FA_LD + k];
            float4 b0 = *(const float4*)(Vs + k * FA_LD + tx * 8);
            float4 b1 = *(const float4*)(Vs + k * FA_LD + tx * 8 + 4);
            float bb[8] = {b0.x, b0.y, b0.z, b0.w, b1.x, b1.y, b1.z, b1.w};
#pragma unroll
            for (int i = 0; i < 4; i++)
#pragma unroll
                for (int j = 0; j < 8; j++)
                    o[i][j] += a[i] * bb[j];
        }
    }

    // epilogue: write [B,T,H*Dh] for the output projection
    const int b = bh >> 4;
    const int h = bh & 15;
#pragma unroll
    for (int i = 0; i < 4; i++) {
        int   t   = it * 64 + ty * 4 + i;
        float inv = 1.0f / l_i[i];
        float* dst = g_O + (size_t)(b * SEQ + t) * D_MODEL + h * HEAD_DIM + tx * 8;
        *(float4*)dst       = make_float4(o[i][0] * inv, o[i][1] * inv,
                                          o[i][2] * inv, o[i][3] * inv);
        *(float4*)(dst + 4) = make_float4(o[i][4] * inv, o[i][5] * inv,
                                          o[i][6] * inv, o[i][7] * inv);
    }
}

// ---------------- launch ----------------------------------------------------
extern "C" void kernel_launch(void* const* d_in, const int* in_sizes, int n_in,
                              void* d_out, int out_size)
{
    const float* x  = (const float*)d_in[0];
    const float* Wq = (const float*)d_in[1];
    const float* Wk = (const float*)d_in[2];
    const float* Wv = (const float*)d_in[3];
    const float* Wo = (const float*)d_in[4];
    float* out = (float*)d_out;

    // 1) fused QKV projections (grid.z selects weight), writes [B,H,T,Dh]
    dim3 gq(D_MODEL / BN, M_ROWS / BM, 3);
    sgemm_kernel<<<gq, 256>>>(x, Wq, Wk, Wv, 0, nullptr);

    // 2) RoPE in place on Q and K
    rope_kernel<<<(BATCH * N_HEADS * SEQ * 32) / 256, 256>>>();

    // 3) causal flash attention -> g_O [B,T,D]
    const int fa_smem = 4 * 64 * FA_LD * (int)sizeof(float);   // 69632 B
    cudaFuncSetAttribute(flash_kernel,
                         cudaFuncAttributeMaxDynamicSharedMemorySize, fa_smem);
    flash_kernel<<<dim3(SEQ / 64, BATCH * N_HEADS), 128, fa_smem>>>();

    // 4) output projection: out = g_O @ Wo^T
    dim3 go(D_MODEL / BN, M_ROWS / BM, 1);
    sgemm_kernel<<<go, 256>>>(nullptr, Wo, nullptr, nullptr, 1, out);
}

// round 4
// speedup vs baseline: 1.5559x; 1.5559x over previous
#include <cuda_runtime.h>
#include <cuda_bf16.h>
#include <math.h>
#include <stdint.h>

#define D_MODEL  1024
#define N_HEADS  16
#define HEAD_DIM 64
#define BATCH    4
#define SEQ      2048
#define M_ROWS   (BATCH * SEQ)   // 8192

// ---------------- scratch (static device arrays; no allocation allowed) ----
__device__ float g_Q[BATCH * N_HEADS * SEQ * HEAD_DIM];   // [B,H,T,Dh]
__device__ float g_K[BATCH * N_HEADS * SEQ * HEAD_DIM];
__device__ float g_V[BATCH * N_HEADS * SEQ * HEAD_DIM];
__device__ float g_O[M_ROWS * D_MODEL];                   // [B,T,D] attn output

// ================= helpers =================================================
__device__ __forceinline__ uint32_t smem_u32(const void* p) {
    uint32_t a;
    asm("{ .reg .u64 t; cvta.to.shared.u64 t, %1; cvt.u32.u64 %0, t; }"
        : "=r"(a) : "l"(p));
    return a;
}
__device__ __forceinline__ void ldsm_x4(uint32_t* r, uint32_t a) {
    asm volatile("ldmatrix.sync.aligned.m8n8.x4.shared.b16 {%0,%1,%2,%3}, [%4];"
                 : "=r"(r[0]), "=r"(r[1]), "=r"(r[2]), "=r"(r[3]) : "r"(a));
}
__device__ __forceinline__ void ldsm_x2(uint32_t* r, uint32_t a) {
    asm volatile("ldmatrix.sync.aligned.m8n8.x2.shared.b16 {%0,%1}, [%2];"
                 : "=r"(r[0]), "=r"(r[1]) : "r"(a));
}
__device__ __forceinline__ void mma16816(float* c, const uint32_t* a,
                                         uint32_t b0, uint32_t b1) {
    asm volatile("mma.sync.aligned.m16n8k16.row.col.f32.bf16.bf16.f32 "
                 "{%0,%1,%2,%3}, {%4,%5,%6,%7}, {%8,%9}, {%0,%1,%2,%3};"
                 : "+f"(c[0]), "+f"(c[1]), "+f"(c[2]), "+f"(c[3])
                 : "r"(a[0]), "r"(a[1]), "r"(a[2]), "r"(a[3]),
                   "r"(b0), "r"(b1));
}
__device__ __forceinline__ uint32_t pack_bf16(float x, float y) {
    __nv_bfloat162 h = __floats2bfloat162_rn(x, y);
    return *(uint32_t*)&h;
}

// ================= HMMA GEMM: C[128,128] tiles of A[M,K] @ W[N,K]^T ========
// bf16 hi/lo split (3 products), fp32 accumulate via mma.sync m16n8k16.
// smem tiles padded to stride 40 bf16 (80B) -> conflict-free ldmatrix.
#define GKC 32          // K per chunk (bf16 elems)
#define LDSR 40         // smem row stride in bf16 elems

__global__ void __launch_bounds__(256, 2)
gemm_mma_kernel(const float* __restrict__ A,
                const float* __restrict__ W0,
                const float* __restrict__ W1,
                const float* __restrict__ W2,
                int mode,                       // 0: QKV->head layout, 1: plain
                float* __restrict__ outPlain)
{
    __shared__ __nv_bfloat16 sAhi[128 * LDSR];
    __shared__ __nv_bfloat16 sAlo[128 * LDSR];
    __shared__ __nv_bfloat16 sBhi[128 * LDSR];
    __shared__ __nv_bfloat16 sBlo[128 * LDSR];

    const int tid  = threadIdx.x;
    const int wid  = tid >> 5;
    const int lane = tid & 31;
    const int wm   = wid >> 2;     // 0..1  (m dir, 64 rows)
    const int wn   = wid & 3;      // 0..3  (n dir, 32 cols)

    const int m0 = blockIdx.y * 128;
    const int n0 = blockIdx.x * 128;

    const float* Aptr;
    const float* W;
    float* dstQKV = nullptr;
    if (mode == 0) {
        Aptr = A;
        if (blockIdx.z == 0)      { W = W0; dstQKV = g_Q; }
        else if (blockIdx.z == 1) { W = W1; dstQKV = g_K; }
        else                      { W = W2; dstQKV = g_V; }
    } else {
        Aptr = g_O;
        W = W0;
    }

    const uint32_t aAhi = smem_u32(sAhi);
    const uint32_t aAlo = smem_u32(sAlo);
    const uint32_t aBhi = smem_u32(sBhi);
    const uint32_t aBlo = smem_u32(sBlo);

    // ldmatrix lane-address components (constant per thread)
    const int rA = wm * 64 + (lane & 7) + ((lane >> 3) & 1) * 8;  // + i*16
    const int cA = ((lane >> 4) & 1) * 8;                          // + ks*16
    const int rB = wn * 32 + (lane & 7);                           // + j*8
    const int cB = ((lane >> 3) & 1) * 8;                          // + ks*16

    float acc[4][4][4];
#pragma unroll
    for (int i = 0; i < 4; i++)
#pragma unroll
        for (int j = 0; j < 4; j++)
#pragma unroll
            for (int q = 0; q < 4; q++) acc[i][j][q] = 0.0f;

    for (int ch = 0; ch < D_MODEL / GKC; ch++) {
        const int k0 = ch * GKC;
        __syncthreads();   // prior chunk's ldmatrix reads done

        // ---- load fp32, split hi/lo bf16, store to smem ----
#pragma unroll
        for (int p = 0; p < 4; p++) {
            int i  = tid + p * 256;        // 0..1023 = 128 rows x 8 float4
            int r  = i >> 3;
            int c4 = (i & 7) << 2;
            int so = r * LDSR + c4;

            float4 av = *(const float4*)(Aptr + (size_t)(m0 + r) * D_MODEL + k0 + c4);
            float hx = __bfloat162float(__float2bfloat16_rn(av.x));
            float hy = __bfloat162float(__float2bfloat16_rn(av.y));
            float hz = __bfloat162float(__float2bfloat16_rn(av.z));
            float hw = __bfloat162float(__float2bfloat16_rn(av.w));
            *(uint2*)(sAhi + so) = make_uint2(pack_bf16(hx, hy), pack_bf16(hz, hw));
            *(uint2*)(sAlo + so) = make_uint2(pack_bf16(av.x - hx, av.y - hy),
                                              pack_bf16(av.z - hz, av.w - hw));

            float4 wv = *(const float4*)(W + (size_t)(n0 + r) * D_MODEL + k0 + c4);
            float gx = __bfloat162float(__float2bfloat16_rn(wv.x));
            float gy = __bfloat162float(__float2bfloat16_rn(wv.y));
            float gz = __bfloat162float(__float2bfloat16_rn(wv.z));
            float gw = __bfloat162float(__float2bfloat16_rn(wv.w));
            *(uint2*)(sBhi + so) = make_uint2(pack_bf16(gx, gy), pack_bf16(gz, gw));
            *(uint2*)(sBlo + so) = make_uint2(pack_bf16(wv.x - gx, wv.y - gy),
                                              pack_bf16(wv.z - gz, wv.w - gw));
        }
        __syncthreads();

        // ---- fragments + mma ----
#pragma unroll
        for (int ks = 0; ks < 2; ks++) {
            uint32_t ah[4][4], al[4][4];
#pragma unroll
            for (int i = 0; i < 4; i++) {
                uint32_t off = (uint32_t)((rA + i * 16) * LDSR + cA + ks * 16) * 2;
                ldsm_x4(ah[i], aAhi + off);
                ldsm_x4(al[i], aAlo + off);
            }
            uint32_t bh[4][2], bl[4][2];
#pragma unroll
            for (int j = 0; j < 4; j++) {
                uint32_t off = (uint32_t)((rB + j * 8) * LDSR + cB + ks * 16) * 2;
                ldsm_x2(bh[j], aBhi + off);
                ldsm_x2(bl[j], aBlo + off);
            }
#pragma unroll
            for (int i = 0; i < 4; i++)
#pragma unroll
                for (int j = 0; j < 4; j++) {
                    mma16816(acc[i][j], ah[i], bh[j][0], bh[j][1]);
                    mma16816(acc[i][j], ah[i], bl[j][0], bl[j][1]);
                    mma16816(acc[i][j], al[i], bh[j][0], bh[j][1]);
                }
        }
    }

    // ---- epilogue: c frag rows m=lane/4 (+8), cols n=2*(lane%4) (+1) ----
#pragma unroll
    for (int i = 0; i < 4; i++) {
#pragma unroll
        for (int j = 0; j < 4; j++) {
            int R0 = m0 + wm * 64 + i * 16 + (lane >> 2);
            int C  = n0 + wn * 32 + j * 8 + (lane & 3) * 2;
            if (mode == 0) {
                int h = C >> 6, d = C & 63;
#pragma unroll
                for (int half = 0; half < 2; half++) {
                    int R = R0 + half * 8;
                    int b = R >> 11, t = R & 2047;
                    float* dst = dstQKV +
                        ((size_t)(b * N_HEADS + h) * SEQ + t) * HEAD_DIM + d;
                    *(float2*)dst = make_float2(acc[i][j][half * 2],
                                                acc[i][j][half * 2 + 1]);
                }
            } else {
#pragma unroll
                for (int half = 0; half < 2; half++) {
                    int R = R0 + half * 8;
                    float* dst = outPlain + (size_t)R * D_MODEL + C;
                    *(float2*)dst = make_float2(acc[i][j][half * 2],
                                                acc[i][j][half * 2 + 1]);
                }
            }
        }
    }
}

// ---------------- RoPE (in-place on g_Q, g_K) ------------------------------
__global__ void __launch_bounds__(256)
rope_kernel()
{
    int idx = blockIdx.x * blockDim.x + threadIdx.x;   // B*H*T*32 = 4194304
    int d  = idx & 31;
    int t  = (idx >> 5) & (SEQ - 1);
    int bh = idx >> 16;

    float inv_freq = expf(-(float)d * 0.28782313662425573f);
    float ang = (float)t * inv_freq;
    float s, c;
    sincosf(ang, &s, &c);

    size_t base = ((size_t)bh * SEQ + t) * HEAD_DIM + d;
    float q1 = g_Q[base], q2 = g_Q[base + 32];
    g_Q[base]      = q1 * c - q2 * s;
    g_Q[base + 32] = q2 * c + q1 * s;
    float k1 = g_K[base], k2 = g_K[base + 32];
    g_K[base]      = k1 * c - k2 * s;
    g_K[base + 32] = k2 * c + k1 * s;
}

// ---------------- Flash attention (causal, fp32) ----------------------------
#define FA_LD 68   // padded row stride in smem

__global__ void __launch_bounds__(128)
flash_kernel()
{
    extern __shared__ float smf[];
    float* Qt = smf;                  // [64][68]  Qt[d][r]
    float* Kt = Qt + 64 * FA_LD;      // [64][68]  Kt[d][c]
    float* Vs = Kt + 64 * FA_LD;      // [64][68]  Vs[k][d]
    float* Ps = Vs + 64 * FA_LD;      // [64][68]  Ps[r][c]

    const int it = (int)gridDim.x - 1 - (int)blockIdx.x;  // heavy tiles first
    const int bh = blockIdx.y;
    const float* Qg = g_Q + (size_t)bh * SEQ * HEAD_DIM;
    const float* Kg = g_K + (size_t)bh * SEQ * HEAD_DIM;
    const float* Vg = g_V + (size_t)bh * SEQ * HEAD_DIM;

    const int tid = threadIdx.x;
    const int tx = tid & 7;
    const int ty = tid >> 3;

#pragma unroll
    for (int p = 0; p < 8; p++) {
        int i  = tid + p * 128;
        int r  = i >> 4;
        int c4 = (i & 15) << 2;
        float4 v = *(const float4*)(Qg + (size_t)(it * 64 + r) * 64 + c4);
        Qt[(c4 + 0) * FA_LD + r] = v.x;
        Qt[(c4 + 1) * FA_LD + r] = v.y;
        Qt[(c4 + 2) * FA_LD + r] = v.z;
        Qt[(c4 + 3) * FA_LD + r] = v.w;
    }

    float o[4][8];
    float m_i[4], l_i[4];
#pragma unroll
    for (int i = 0; i < 4; i++) {
        m_i[i] = -INFINITY; l_i[i] = 0.0f;
#pragma unroll
        for (int j = 0; j < 8; j++) o[i][j] = 0.0f;
    }

    for (int jt = 0; jt <= it; jt++) {
        __syncthreads();
#pragma unroll
        for (int p = 0; p < 8; p++) {
            int i  = tid + p * 128;
            int r  = i >> 4;
            int c4 = (i & 15) << 2;
            float4 kv = *(const float4*)(Kg + (size_t)(jt * 64 + r) * 64 + c4);
            Kt[(c4 + 0) * FA_LD + r] = kv.x;
            Kt[(c4 + 1) * FA_LD + r] = kv.y;
            Kt[(c4 + 2) * FA_LD + r] = kv.z;
            Kt[(c4 + 3) * FA_LD + r] = kv.w;
            float4 vv = *(const float4*)(Vg + (size_t)(jt * 64 + r) * 64 + c4);
            *(float4*)(Vs + r * FA_LD + c4) = vv;
        }
        __syncthreads();

        float s[4][8];
#pragma unroll
        for (int i = 0; i < 4; i++)
#pragma unroll
            for (int j = 0; j < 8; j++) s[i][j] = 0.0f;

#pragma unroll 8
        for (int d = 0; d < 64; d++) {
            float4 aq = *(const float4*)(Qt + d * FA_LD + ty * 4);
            float4 b0 = *(const float4*)(Kt + d * FA_LD + tx * 8);
            float4 b1 = *(const float4*)(Kt + d * FA_LD + tx * 8 + 4);
            float a[4]  = {aq.x, aq.y, aq.z, aq.w};
            float bb[8] = {b0.x, b0.y, b0.z, b0.w, b1.x, b1.y, b1.z, b1.w};
#pragma unroll
            for (int i = 0; i < 4; i++)
#pragma unroll
                for (int j = 0; j < 8; j++)
                    s[i][j] += a[i] * bb[j];
        }

        if (jt == it) {
#pragma unroll
            for (int i = 0; i < 4; i++)
#pragma unroll
                for (int j = 0; j < 8; j++) {
                    if (tx * 8 + j > ty * 4 + i) s[i][j] = -INFINITY;
                    else                         s[i][j] *= 0.125f;
                }
        } else {
#pragma unroll
            for (int i = 0; i < 4; i++)
#pragma unroll
                for (int j = 0; j < 8; j++) s[i][j] *= 0.125f;
        }

#pragma unroll
        for (int i = 0; i < 4; i++) {
            float mt = s[i][0];
#pragma unroll
            for (int j = 1; j < 8; j++) mt = fmaxf(mt, s[i][j]);
            mt = fmaxf(mt, __shfl_xor_sync(0xffffffffu, mt, 1));
            mt = fmaxf(mt, __shfl_xor_sync(0xffffffffu, mt, 2));
            mt = fmaxf(mt, __shfl_xor_sync(0xffffffffu, mt, 4));

            float mn   = fmaxf(m_i[i], mt);
            float resc = __expf(m_i[i] - mn);
            m_i[i] = mn;

            float rs = 0.0f;
#pragma unroll
            for (int j = 0; j < 8; j++) {
                float p = __expf(s[i][j] - mn);
                s[i][j] = p;
                rs += p;
            }
            rs += __shfl_xor_sync(0xffffffffu, rs, 1);
            rs += __shfl_xor_sync(0xffffffffu, rs, 2);
            rs += __shfl_xor_sync(0xffffffffu, rs, 4);

            l_i[i] = l_i[i] * resc + rs;
#pragma unroll
            for (int j = 0; j < 8; j++) o[i][j] *= resc;
        }

#pragma unroll
        for (int i = 0; i < 4; i++) {
            float* pr = Ps + (ty * 4 + i) * FA_LD + tx * 8;
            *(float4*)pr       = make_float4(s[i][0], s[i][1], s[i][2], s[i][3]);
            *(float4*)(pr + 4) = make_float4(s[i][4], s[i][5], s[i][6], s[i][7]);
        }
        __syncthreads();

#pragma unroll 8
        for (int k = 0; k < 64; k++) {
            float a[4];
#pragma unroll
            for (int i = 0; i < 4; i++) a[i] = Ps[(ty * 4 + i) * FA_LD + k];
            float4 b0 = *(const float4*)(Vs + k * FA_LD + tx * 8);
            float4 b1 = *(const float4*)(Vs + k * FA_LD + tx * 8 + 4);
            float bb[8] = {b0.x, b0.y, b0.z, b0.w, b1.x, b1.y, b1.z, b1.w};
#pragma unroll
            for (int i = 0; i < 4; i++)
#pragma unroll
                for (int j = 0; j < 8; j++)
                    o[i][j] += a[i] * bb[j];
        }
    }

    const int b = bh >> 4;
    const int h = bh & 15;
#pragma unroll
    for (int i = 0; i < 4; i++) {
        int   t   = it * 64 + ty * 4 + i;
        float inv = 1.0f / l_i[i];
        float* dst = g_O + (size_t)(b * SEQ + t) * D_MODEL + h * HEAD_DIM + tx * 8;
        *(float4*)dst       = make_float4(o[i][0] * inv, o[i][1] * inv,
                                          o[i][2] * inv, o[i][3] * inv);
        *(float4*)(dst + 4) = make_float4(o[i][4] * inv, o[i][5] * inv,
                                          o[i][6] * inv, o[i][7] * inv);
    }
}

// ---------------- launch ----------------------------------------------------
extern "C" void kernel_launch(void* const* d_in, const int* in_sizes, int n_in,
                              void* d_out, int out_size)
{
    const float* x  = (const float*)d_in[0];
    const float* Wq = (const float*)d_in[1];
    const float* Wk = (const float*)d_in[2];
    const float* Wv = (const float*)d_in[3];
    const float* Wo = (const float*)d_in[4];
    float* out = (float*)d_out;

    // 1) fused QKV projections via HMMA (grid.z selects weight)
    dim3 gq(D_MODEL / 128, M_ROWS / 128, 3);
    gemm_mma_kernel<<<gq, 256>>>(x, Wq, Wk, Wv, 0, nullptr);

    // 2) RoPE in place on Q and K
    rope_kernel<<<(BATCH * N_HEADS * SEQ * 32) / 256, 256>>>();

    // 3) causal flash attention -> g_O [B,T,D]
    const int fa_smem = 4 * 64 * FA_LD * (int)sizeof(float);   // 69632 B
    cudaFuncSetAttribute(flash_kernel,
                         cudaFuncAttributeMaxDynamicSharedMemorySize, fa_smem);
    flash_kernel<<<dim3(SEQ / 64, BATCH * N_HEADS), 128, fa_smem>>>();

    // 4) output projection: out = g_O @ Wo^T  (HMMA)
    dim3 go(D_MODEL / 128, M_ROWS / 128, 1);
    gemm_mma_kernel<<<go, 256>>>(nullptr, Wo, nullptr, nullptr, 1, out);
}

// round 5
// speedup vs baseline: 2.0997x; 1.3496x over previous
#include <cuda_runtime.h>
#include <cuda_bf16.h>
#include <math.h>
#include <stdint.h>

#define D_MODEL  1024
#define N_HEADS  16
#define HEAD_DIM 64
#define BATCH    4
#define SEQ      2048
#define M_ROWS   (BATCH * SEQ)   // 8192
#define NELEM    (BATCH * N_HEADS * SEQ * HEAD_DIM)   // 8388608

// ---------------- scratch (static device arrays; no allocation allowed) ----
__device__ float g_Q[NELEM];                 // [B,H,T,Dh] fp32 (pre-rope)
__device__ float g_K[NELEM];
__device__ float g_O[M_ROWS * D_MODEL];      // [B,T,D] attn output fp32
__device__ __nv_bfloat16 g_Qh[NELEM], g_Ql[NELEM];   // post-rope split
__device__ __nv_bfloat16 g_Kh[NELEM], g_Kl[NELEM];
__device__ __nv_bfloat16 g_Vh[NELEM], g_Vl[NELEM];   // split V from GEMM

// ================= helpers =================================================
__device__ __forceinline__ uint32_t smem_u32(const void* p) {
    uint32_t a;
    asm("{ .reg .u64 t; cvta.to.shared.u64 t, %1; cvt.u32.u64 %0, t; }"
        : "=r"(a) : "l"(p));
    return a;
}
__device__ __forceinline__ void ldsm_x4(uint32_t* r, uint32_t a) {
    asm volatile("ldmatrix.sync.aligned.m8n8.x4.shared.b16 {%0,%1,%2,%3}, [%4];"
                 : "=r"(r[0]), "=r"(r[1]), "=r"(r[2]), "=r"(r[3]) : "r"(a));
}
__device__ __forceinline__ void ldsm_x4_t(uint32_t* r, uint32_t a) {
    asm volatile("ldmatrix.sync.aligned.m8n8.x4.trans.shared.b16 {%0,%1,%2,%3}, [%4];"
                 : "=r"(r[0]), "=r"(r[1]), "=r"(r[2]), "=r"(r[3]) : "r"(a));
}
__device__ __forceinline__ void ldsm_x2(uint32_t* r, uint32_t a) {
    asm volatile("ldmatrix.sync.aligned.m8n8.x2.shared.b16 {%0,%1}, [%2];"
                 : "=r"(r[0]), "=r"(r[1]) : "r"(a));
}
__device__ __forceinline__ void mma16816(float* c, const uint32_t* a,
                                         uint32_t b0, uint32_t b1) {
    asm volatile("mma.sync.aligned.m16n8k16.row.col.f32.bf16.bf16.f32 "
                 "{%0,%1,%2,%3}, {%4,%5,%6,%7}, {%8,%9}, {%0,%1,%2,%3};"
                 : "+f"(c[0]), "+f"(c[1]), "+f"(c[2]), "+f"(c[3])
                 : "r"(a[0]), "r"(a[1]), "r"(a[2]), "r"(a[3]),
                   "r"(b0), "r"(b1));
}
__device__ __forceinline__ uint32_t pack_bf16(float x, float y) {
    __nv_bfloat162 h = __floats2bfloat162_rn(x, y);
    return *(uint32_t*)&h;
}
__device__ __forceinline__ void split2(float x, float y,
                                       uint32_t& hi, uint32_t& lo) {
    __nv_bfloat162 h = __floats2bfloat162_rn(x, y);
    hi = *(uint32_t*)&h;
    __nv_bfloat162 l = __floats2bfloat162_rn(x - __bfloat162float(h.x),
                                             y - __bfloat162float(h.y));
    lo = *(uint32_t*)&l;
}

// ================= HMMA GEMM: C[128,128] tiles of A[M,K] @ W[N,K]^T ========
#define GKC 32
#define LDSR 40

__global__ void __launch_bounds__(256, 2)
gemm_mma_kernel(const float* __restrict__ A,
                const float* __restrict__ W0,
                const float* __restrict__ W1,
                const float* __restrict__ W2,
                int mode,                       // 0: QKV, 1: plain out
                float* __restrict__ outPlain)
{
    __shared__ __nv_bfloat16 sAhi[128 * LDSR];
    __shared__ __nv_bfloat16 sAlo[128 * LDSR];
    __shared__ __nv_bfloat16 sBhi[128 * LDSR];
    __shared__ __nv_bfloat16 sBlo[128 * LDSR];

    const int tid  = threadIdx.x;
    const int wid  = tid >> 5;
    const int lane = tid & 31;
    const int wm   = wid >> 2;
    const int wn   = wid & 3;

    const int m0 = blockIdx.y * 128;
    const int n0 = blockIdx.x * 128;

    const float* Aptr;
    const float* W;
    float* dstF = nullptr;
    int isV = 0;
    if (mode == 0) {
        Aptr = A;
        if (blockIdx.z == 0)      { W = W0; dstF = g_Q; }
        else if (blockIdx.z == 1) { W = W1; dstF = g_K; }
        else                      { W = W2; isV = 1; }
    } else {
        Aptr = g_O;
        W = W0;
    }

    const uint32_t aAhi = smem_u32(sAhi);
    const uint32_t aAlo = smem_u32(sAlo);
    const uint32_t aBhi = smem_u32(sBhi);
    const uint32_t aBlo = smem_u32(sBlo);

    const int rA = wm * 64 + (lane & 7) + ((lane >> 3) & 1) * 8;
    const int cA = ((lane >> 4) & 1) * 8;
    const int rB = wn * 32 + (lane & 7);
    const int cB = ((lane >> 3) & 1) * 8;

    float acc[4][4][4];
#pragma unroll
    for (int i = 0; i < 4; i++)
#pragma unroll
        for (int j = 0; j < 4; j++)
#pragma unroll
            for (int q = 0; q < 4; q++) acc[i][j][q] = 0.0f;

    for (int ch = 0; ch < D_MODEL / GKC; ch++) {
        const int k0 = ch * GKC;
        __syncthreads();

#pragma unroll
        for (int p = 0; p < 4; p++) {
            int i  = tid + p * 256;
            int r  = i >> 3;
            int c4 = (i & 7) << 2;
            int so = r * LDSR + c4;

            float4 av = *(const float4*)(Aptr + (size_t)(m0 + r) * D_MODEL + k0 + c4);
            float hx = __bfloat162float(__float2bfloat16_rn(av.x));
            float hy = __bfloat162float(__float2bfloat16_rn(av.y));
            float hz = __bfloat162float(__float2bfloat16_rn(av.z));
            float hw = __bfloat162float(__float2bfloat16_rn(av.w));
            *(uint2*)(sAhi + so) = make_uint2(pack_bf16(hx, hy), pack_bf16(hz, hw));
            *(uint2*)(sAlo + so) = make_uint2(pack_bf16(av.x - hx, av.y - hy),
                                              pack_bf16(av.z - hz, av.w - hw));

            float4 wv = *(const float4*)(W + (size_t)(n0 + r) * D_MODEL + k0 + c4);
            float gx = __bfloat162float(__float2bfloat16_rn(wv.x));
            float gy = __bfloat162float(__float2bfloat16_rn(wv.y));
            float gz = __bfloat162float(__float2bfloat16_rn(wv.z));
            float gw = __bfloat162float(__float2bfloat16_rn(wv.w));
            *(uint2*)(sBhi + so) = make_uint2(pack_bf16(gx, gy), pack_bf16(gz, gw));
            *(uint2*)(sBlo + so) = make_uint2(pack_bf16(wv.x - gx, wv.y - gy),
                                              pack_bf16(wv.z - gz, wv.w - gw));
        }
        __syncthreads();

#pragma unroll
        for (int ks = 0; ks < 2; ks++) {
            uint32_t ah[4][4], al[4][4];
#pragma unroll
            for (int i = 0; i < 4; i++) {
                uint32_t off = (uint32_t)((rA + i * 16) * LDSR + cA + ks * 16) * 2;
                ldsm_x4(ah[i], aAhi + off);
                ldsm_x4(al[i], aAlo + off);
            }
            uint32_t bh[4][2], bl[4][2];
#pragma unroll
            for (int j = 0; j < 4; j++) {
                uint32_t off = (uint32_t)((rB + j * 8) * LDSR + cB + ks * 16) * 2;
                ldsm_x2(bh[j], aBhi + off);
                ldsm_x2(bl[j], aBlo + off);
            }
#pragma unroll
            for (int i = 0; i < 4; i++)
#pragma unroll
                for (int j = 0; j < 4; j++) {
                    mma16816(acc[i][j], ah[i], bh[j][0], bh[j][1]);
                    mma16816(acc[i][j], ah[i], bl[j][0], bl[j][1]);
                    mma16816(acc[i][j], al[i], bh[j][0], bh[j][1]);
                }
        }
    }

#pragma unroll
    for (int i = 0; i < 4; i++) {
#pragma unroll
        for (int j = 0; j < 4; j++) {
            int R0 = m0 + wm * 64 + i * 16 + (lane >> 2);
            int C  = n0 + wn * 32 + j * 8 + (lane & 3) * 2;
            if (mode == 0) {
                int hh = C >> 6, d = C & 63;
#pragma unroll
                for (int half = 0; half < 2; half++) {
                    int R = R0 + half * 8;
                    int b = R >> 11, t = R & 2047;
                    size_t o = ((size_t)(b * N_HEADS + hh) * SEQ + t) * HEAD_DIM + d;
                    float v0 = acc[i][j][half * 2], v1 = acc[i][j][half * 2 + 1];
                    if (isV) {
                        __nv_bfloat162 vh = __floats2bfloat162_rn(v0, v1);
                        __nv_bfloat162 vl = __floats2bfloat162_rn(
                            v0 - __bfloat162float(vh.x), v1 - __bfloat162float(vh.y));
                        *(__nv_bfloat162*)(g_Vh + o) = vh;
                        *(__nv_bfloat162*)(g_Vl + o) = vl;
                    } else {
                        *(float2*)(dstF + o) = make_float2(v0, v1);
                    }
                }
            } else {
#pragma unroll
                for (int half = 0; half < 2; half++) {
                    int R = R0 + half * 8;
                    float* dst = outPlain + (size_t)R * D_MODEL + C;
                    *(float2*)dst = make_float2(acc[i][j][half * 2],
                                                acc[i][j][half * 2 + 1]);
                }
            }
        }
    }
}

// ---------------- RoPE + bf16 hi/lo split ----------------------------------
__global__ void __launch_bounds__(256)
rope_split_kernel()
{
    int idx = blockIdx.x * blockDim.x + threadIdx.x;   // B*H*T*32
    int d  = idx & 31;
    int t  = (idx >> 5) & (SEQ - 1);
    int bh = idx >> 16;

    float inv_freq = expf(-(float)d * 0.28782313662425573f);
    float ang = (float)t * inv_freq;
    float s, c;
    sincosf(ang, &s, &c);

    size_t base = ((size_t)bh * SEQ + t) * HEAD_DIM + d;
    float q1 = g_Q[base], q2 = g_Q[base + 32];
    float qa = q1 * c - q2 * s;
    float qb = q2 * c + q1 * s;
    float k1 = g_K[base], k2 = g_K[base + 32];
    float ka = k1 * c - k2 * s;
    float kb = k2 * c + k1 * s;

    __nv_bfloat16 h;
    h = __float2bfloat16_rn(qa); g_Qh[base] = h;      g_Ql[base]      = __float2bfloat16_rn(qa - __bfloat162float(h));
    h = __float2bfloat16_rn(qb); g_Qh[base + 32] = h; g_Ql[base + 32] = __float2bfloat16_rn(qb - __bfloat162float(h));
    h = __float2bfloat16_rn(ka); g_Kh[base] = h;      g_Kl[base]      = __float2bfloat16_rn(ka - __bfloat162float(h));
    h = __float2bfloat16_rn(kb); g_Kh[base + 32] = h; g_Kl[base + 32] = __float2bfloat16_rn(kb - __bfloat162float(h));
}

// ---------------- Flash attention (causal, HMMA bf16 split) -----------------
// CTA: 128 q-rows, 8 warps (16 rows each); KV tiles of 64 rows.
#define FLD 72   // smem row stride (bf16 elems); 144B: 16B-aligned, cf ldmatrix

__global__ void __launch_bounds__(256)
flash_mma_kernel()
{
    extern __shared__ __nv_bfloat16 sb[];
    __nv_bfloat16* sQh = sb;                 // [128][72]
    __nv_bfloat16* sQl = sb + 9216;
    __nv_bfloat16* sKh = sb + 18432;         // [64][72]
    __nv_bfloat16* sKl = sb + 23040;
    __nv_bfloat16* sVh = sb + 27648;
    __nv_bfloat16* sVl = sb + 32256;

    const int tid  = threadIdx.x;
    const int wid  = tid >> 5;
    const int lane = tid & 31;
    const int it   = (int)gridDim.x - 1 - (int)blockIdx.x;   // heavy first
    const int bh   = blockIdx.y;
    const size_t base = (size_t)bh * SEQ * HEAD_DIM;

    const uint32_t aQh = smem_u32(sQh);
    const uint32_t aQl = aQh + 18432;
    const uint32_t aKh = aQh + 36864;
    const uint32_t aKl = aQh + 46080;
    const uint32_t aVh = aQh + 55296;
    const uint32_t aVl = aQh + 64512;

    // ---- load Q tile (128x64 hi/lo) ----
    {
        const __nv_bfloat16* qh = g_Qh + base + (size_t)it * 128 * 64;
        const __nv_bfloat16* ql = g_Ql + base + (size_t)it * 128 * 64;
#pragma unroll
        for (int p = 0; p < 4; p++) {
            int g = tid + p * 256;          // 0..1023
            int r = g >> 3, c8 = (g & 7) * 8;
            *(uint4*)(sQh + r * FLD + c8) = *(const uint4*)(qh + r * 64 + c8);
            *(uint4*)(sQl + r * FLD + c8) = *(const uint4*)(ql + r * 64 + c8);
        }
    }
    __syncthreads();

    // ---- Q fragments, register-resident ----
    uint32_t qh[4][4], ql[4][4];
    {
        int rA = (lane & 7) + ((lane >> 3) & 1) * 8;
        int cA = ((lane >> 4) & 1) * 8;
#pragma unroll
        for (int ks = 0; ks < 4; ks++) {
            uint32_t off = (uint32_t)((wid * 16 + rA) * FLD + ks * 16 + cA) * 2;
            ldsm_x4(qh[ks], aQh + off);
            ldsm_x4(ql[ks], aQl + off);
        }
    }

    float accO[8][4];
#pragma unroll
    for (int j = 0; j < 8; j++)
#pragma unroll
        for (int q = 0; q < 4; q++) accO[j][q] = 0.0f;
    float m0 = -1e30f, m1 = -1e30f, l0 = 0.0f, l1 = 0.0f;

    const int rowK = (lane & 7) + ((lane >> 4) & 1) * 8;
    const int colK = ((lane >> 3) & 1) * 8;
    const int rowV = (lane & 15);
    const int colV = (lane >> 4) * 8;

    const int jt_end = 2 * it + 1;
    for (int jt = 0; jt <= jt_end; jt++) {
        __syncthreads();
        {
            const size_t kb = base + (size_t)jt * 64 * 64;
#pragma unroll
            for (int p = 0; p < 2; p++) {
                int g = tid + p * 256;      // 0..511
                int r = g >> 3, c8 = (g & 7) * 8;
                *(uint4*)(sKh + r * FLD + c8) = *(const uint4*)(g_Kh + kb + r * 64 + c8);
                *(uint4*)(sKl + r * FLD + c8) = *(const uint4*)(g_Kl + kb + r * 64 + c8);
                *(uint4*)(sVh + r * FLD + c8) = *(const uint4*)(g_Vh + kb + r * 64 + c8);
                *(uint4*)(sVl + r * FLD + c8) = *(const uint4*)(g_Vl + kb + r * 64 + c8);
            }
        }
        __syncthreads();

        // ---- S = Q @ K^T (8 n-tiles per warp) ----
        float s[8][4];
#pragma unroll
        for (int j = 0; j < 8; j++)
#pragma unroll
            for (int q = 0; q < 4; q++) s[j][q] = 0.0f;

#pragma unroll
        for (int ks = 0; ks < 4; ks++) {
#pragma unroll
            for (int pr = 0; pr < 4; pr++) {
                uint32_t kh4[4], kl4[4];
                uint32_t off = (uint32_t)((pr * 16 + rowK) * FLD + ks * 16 + colK) * 2;
                ldsm_x4(kh4, aKh + off);
                ldsm_x4(kl4, aKl + off);
                mma16816(s[2 * pr],     qh[ks], kh4[0], kh4[1]);
                mma16816(s[2 * pr],     ql[ks], kh4[0], kh4[1]);
                mma16816(s[2 * pr],     qh[ks], kl4[0], kl4[1]);
                mma16816(s[2 * pr + 1], qh[ks], kh4[2], kh4[3]);
                mma16816(s[2 * pr + 1], ql[ks], kh4[2], kh4[3]);
                mma16816(s[2 * pr + 1], qh[ks], kl4[2], kl4[3]);
            }
        }

        // ---- causal mask (only boundary tiles) ----
        if (jt >= 2 * it) {
            int row0 = it * 128 + wid * 16 + (lane >> 2);
#pragma unroll
            for (int j = 0; j < 8; j++) {
                int col = jt * 64 + j * 8 + (lane & 3) * 2;
                if (col     > row0)     s[j][0] = -1e30f;
                if (col + 1 > row0)     s[j][1] = -1e30f;
                if (col     > row0 + 8) s[j][2] = -1e30f;
                if (col + 1 > row0 + 8) s[j][3] = -1e30f;
            }
        }

        // ---- online softmax (rows r, r+8; 4-lane groups share a row) ----
        float mx0 = -1e30f, mx1 = -1e30f;
#pragma unroll
        for (int j = 0; j < 8; j++) {
            mx0 = fmaxf(mx0, fmaxf(s[j][0], s[j][1]));
            mx1 = fmaxf(mx1, fmaxf(s[j][2], s[j][3]));
        }
        mx0 = fmaxf(mx0, __shfl_xor_sync(0xffffffffu, mx0, 1));
        mx0 = fmaxf(mx0, __shfl_xor_sync(0xffffffffu, mx0, 2));
        mx1 = fmaxf(mx1, __shfl_xor_sync(0xffffffffu, mx1, 1));
        mx1 = fmaxf(mx1, __shfl_xor_sync(0xffffffffu, mx1, 2));
        float m0n = fmaxf(m0, mx0), m1n = fmaxf(m1, mx1);
        float r0 = __expf((m0 - m0n) * 0.125f);
        float r1 = __expf((m1 - m1n) * 0.125f);
        m0 = m0n; m1 = m1n;
        float nb0 = -m0n * 0.125f, nb1 = -m1n * 0.125f;
        float rs0 = 0.0f, rs1 = 0.0f;
#pragma unroll
        for (int j = 0; j < 8; j++) {
            s[j][0] = __expf(fmaf(s[j][0], 0.125f, nb0));
            s[j][1] = __expf(fmaf(s[j][1], 0.125f, nb0));
            s[j][2] = __expf(fmaf(s[j][2], 0.125f, nb1));
            s[j][3] = __expf(fmaf(s[j][3], 0.125f, nb1));
            rs0 += s[j][0] + s[j][1];
            rs1 += s[j][2] + s[j][3];
        }
        rs0 += __shfl_xor_sync(0xffffffffu, rs0, 1);
        rs0 += __shfl_xor_sync(0xffffffffu, rs0, 2);
        rs1 += __shfl_xor_sync(0xffffffffu, rs1, 1);
        rs1 += __shfl_xor_sync(0xffffffffu, rs1, 2);
        l0 = l0 * r0 + rs0;
        l1 = l1 * r1 + rs1;
#pragma unroll
        for (int j = 0; j < 8; j++) {
            accO[j][0] *= r0; accO[j][1] *= r0;
            accO[j][2] *= r1; accO[j][3] *= r1;
        }

        // ---- O += P @ V  (P C-frags re-pack directly into A-frags) ----
#pragma unroll
        for (int ks = 0; ks < 4; ks++) {
            uint32_t ph[4], pl[4];
            split2(s[2 * ks][0],     s[2 * ks][1],     ph[0], pl[0]);
            split2(s[2 * ks][2],     s[2 * ks][3],     ph[1], pl[1]);
            split2(s[2 * ks + 1][0], s[2 * ks + 1][1], ph[2], pl[2]);
            split2(s[2 * ks + 1][2], s[2 * ks + 1][3], ph[3], pl[3]);
#pragma unroll
            for (int dp = 0; dp < 4; dp++) {
                uint32_t vh4[4], vl4[4];
                uint32_t off = (uint32_t)((ks * 16 + rowV) * FLD + dp * 16 + colV) * 2;
                ldsm_x4_t(vh4, aVh + off);
                ldsm_x4_t(vl4, aVl + off);
                mma16816(accO[2 * dp],     ph, vh4[0], vh4[1]);
                mma16816(accO[2 * dp],     pl, vh4[0], vh4[1]);
                mma16816(accO[2 * dp],     ph, vl4[0], vl4[1]);
                mma16816(accO[2 * dp + 1], ph, vh4[2], vh4[3]);
                mma16816(accO[2 * dp + 1], pl, vh4[2], vh4[3]);
                mma16816(accO[2 * dp + 1], ph, vl4[2], vl4[3]);
            }
        }
    }

    // ---- epilogue: O / l -> g_O [B,T,D] ----
    float i0 = 1.0f / l0, i1 = 1.0f / l1;
    const int b = bh >> 4, hh = bh & 15;
    const int t0 = it * 128 + wid * 16 + (lane >> 2);
#pragma unroll
    for (int j = 0; j < 8; j++) {
        int d = hh * 64 + j * 8 + (lane & 3) * 2;
        *(float2*)(g_O + (size_t)(b * SEQ + t0) * D_MODEL + d) =
            make_float2(accO[j][0] * i0, accO[j][1] * i0);
        *(float2*)(g_O + (size_t)(b * SEQ + t0 + 8) * D_MODEL + d) =
            make_float2(accO[j][2] * i1, accO[j][3] * i1);
    }
}

// ---------------- launch ----------------------------------------------------
extern "C" void kernel_launch(void* const* d_in, const int* in_sizes, int n_in,
                              void* d_out, int out_size)
{
    const float* x  = (const float*)d_in[0];
    const float* Wq = (const float*)d_in[1];
    const float* Wk = (const float*)d_in[2];
    const float* Wv = (const float*)d_in[3];
    const float* Wo = (const float*)d_in[4];
    float* out = (float*)d_out;

    // 1) fused QKV projections via HMMA (V written pre-split bf16)
    dim3 gq(D_MODEL / 128, M_ROWS / 128, 3);
    gemm_mma_kernel<<<gq, 256>>>(x, Wq, Wk, Wv, 0, nullptr);

    // 2) RoPE + hi/lo split on Q and K
    rope_split_kernel<<<(BATCH * N_HEADS * SEQ * 32) / 256, 256>>>();

    // 3) causal flash attention (HMMA) -> g_O [B,T,D]
    const int fa_smem = 36864 * 2;   // 73728 B
    cudaFuncSetAttribute(flash_mma_kernel,
                         cudaFuncAttributeMaxDynamicSharedMemorySize, fa_smem);
    flash_mma_kernel<<<dim3(SEQ / 128, BATCH * N_HEADS), 256, fa_smem>>>();

    // 4) output projection: out = g_O @ Wo^T  (HMMA)
    dim3 go(D_MODEL / 128, M_ROWS / 128, 1);
    gemm_mma_kernel<<<go, 256>>>(nullptr, Wo, nullptr, nullptr, 1, out);
}

// round 7
// speedup vs baseline: 3.4744x; 1.6547x over previous
#include <cuda_runtime.h>
#include <cuda_bf16.h>
#include <math.h>
#include <stdint.h>

#define D_MODEL  1024
#define N_HEADS  16
#define HEAD_DIM 64
#define BATCH    4
#define SEQ      2048
#define M_ROWS   (BATCH * SEQ)   // 8192
#define NELEM    (BATCH * N_HEADS * SEQ * HEAD_DIM)   // 8388608

// ---------------- scratch (static device arrays; no allocation allowed) ----
__device__ float g_Q[NELEM];                 // [B,H,T,Dh] fp32 (pre-rope)
__device__ float g_K[NELEM];
__device__ __nv_bfloat16 g_Xh[NELEM], g_Xl[NELEM];             // split x
__device__ __nv_bfloat16 g_Wh[4 * 1024 * 1024], g_Wl[4 * 1024 * 1024]; // q,k,v,o
__device__ __nv_bfloat16 g_Qh[NELEM], g_Ql[NELEM];             // post-rope split
__device__ __nv_bfloat16 g_Kh[NELEM], g_Kl[NELEM];
__device__ __nv_bfloat16 g_Vh[NELEM], g_Vl[NELEM];             // split V
__device__ __nv_bfloat16 g_Oh[NELEM], g_Ol[NELEM];             // split attn out

// ================= helpers =================================================
__device__ __forceinline__ uint32_t smem_u32(const void* p) {
    uint32_t a;
    asm("{ .reg .u64 t; cvta.to.shared.u64 t, %1; cvt.u32.u64 %0, t; }"
        : "=r"(a) : "l"(p));
    return a;
}
__device__ __forceinline__ void ldsm_x4(uint32_t* r, uint32_t a) {
    asm volatile("ldmatrix.sync.aligned.m8n8.x4.shared.b16 {%0,%1,%2,%3}, [%4];"
                 : "=r"(r[0]), "=r"(r[1]), "=r"(r[2]), "=r"(r[3]) : "r"(a));
}
__device__ __forceinline__ void ldsm_x4_t(uint32_t* r, uint32_t a) {
    asm volatile("ldmatrix.sync.aligned.m8n8.x4.trans.shared.b16 {%0,%1,%2,%3}, [%4];"
                 : "=r"(r[0]), "=r"(r[1]), "=r"(r[2]), "=r"(r[3]) : "r"(a));
}
__device__ __forceinline__ void mma16816(float* c, const uint32_t* a,
                                         uint32_t b0, uint32_t b1) {
    asm volatile("mma.sync.aligned.m16n8k16.row.col.f32.bf16.bf16.f32 "
                 "{%0,%1,%2,%3}, {%4,%5,%6,%7}, {%8,%9}, {%0,%1,%2,%3};"
                 : "+f"(c[0]), "+f"(c[1]), "+f"(c[2]), "+f"(c[3])
                 : "r"(a[0]), "r"(a[1]), "r"(a[2]), "r"(a[3]),
                   "r"(b0), "r"(b1));
}
__device__ __forceinline__ void split2(float x, float y,
                                       uint32_t& hi, uint32_t& lo) {
    __nv_bfloat162 h = __floats2bfloat162_rn(x, y);
    hi = *(uint32_t*)&h;
    __nv_bfloat162 l = __floats2bfloat162_rn(x - __bfloat162float(h.x),
                                             y - __bfloat162float(h.y));
    lo = *(uint32_t*)&l;
}
__device__ __forceinline__ void split4_store(__nv_bfloat16* dh, __nv_bfloat16* dl,
                                             float4 v) {
    uint32_t h0, l0, h1, l1;
    split2(v.x, v.y, h0, l0);
    split2(v.z, v.w, h1, l1);
    *(uint2*)dh = make_uint2(h0, h1);
    *(uint2*)dl = make_uint2(l0, l1);
}

// ================= one-shot split kernels ==================================
__global__ void __launch_bounds__(256)
split_x_kernel(const float* __restrict__ x)
{
    int i = blockIdx.x * 256 + threadIdx.x;     // < NELEM/4 (float4s)
    float4 v = ((const float4*)x)[i];
    size_t o = (size_t)i * 4;
    split4_store(g_Xh + o, g_Xl + o, v);
}

__global__ void __launch_bounds__(256)
split_w_kernel(const float* __restrict__ Wq, const float* __restrict__ Wk,
               const float* __restrict__ Wv, const float* __restrict__ Wo)
{
    int i = blockIdx.x * 256 + threadIdx.x;     // < 4M/4 = 1M float4s
    int s = i >> 18;                            // 256K float4 per matrix
    const float* src = (s == 0) ? Wq : (s == 1) ? Wk : (s == 2) ? Wv : Wo;
    float4 v = ((const float4*)src)[i & 0x3FFFF];
    size_t o = (size_t)i * 4;
    split4_store(g_Wh + o, g_Wl + o, v);
}

// ================= HMMA GEMM on pre-split bf16 =============================
// C[128,128] tiles of A[M,1024] @ W[1024,1024]^T ; 3-product hi/lo split.
// a_sel: 0 -> A = g_Xh/g_Xl (QKV, grid.z selects W slot 0..2, head layout out)
//        1 -> A = g_Oh/g_Ol (out-proj, W slot 3, plain fp32 out)
#define GKC  64
#define LDSR 72
#define GEMM_SMEM (4 * 128 * LDSR * 2)   // 73728 B

__global__ void __launch_bounds__(256, 2)
gemm_bf16_kernel(int a_sel, float* __restrict__ outPlain)
{
    extern __shared__ __nv_bfloat16 ds[];
    __nv_bfloat16* sAh = ds;
    __nv_bfloat16* sAl = ds + 9216;
    __nv_bfloat16* sBh = ds + 18432;
    __nv_bfloat16* sBl = ds + 27648;

    const int tid  = threadIdx.x;
    const int wid  = tid >> 5;
    const int lane = tid & 31;
    const int wm   = wid >> 2;
    const int wn   = wid & 3;

    const int m0 = blockIdx.y * 128;
    const int n0 = blockIdx.x * 128;

    const __nv_bfloat16* Ah = a_sel ? g_Oh : g_Xh;
    const __nv_bfloat16* Al = a_sel ? g_Ol : g_Xl;

    const int slot = a_sel ? 3 : (int)blockIdx.z;
    const __nv_bfloat16* Wh = g_Wh + ((size_t)slot << 20);
    const __nv_bfloat16* Wl = g_Wl + ((size_t)slot << 20);

    float* dstF = (slot == 0) ? g_Q : g_K;
    const int isV = (slot == 2);

    const uint32_t aAh = smem_u32(sAh);
    const uint32_t aAl = aAh + 18432;
    const uint32_t aBh = aAh + 36864;
    const uint32_t aBl = aAh + 55296;

    const int rA   = wm * 64 + (lane & 7) + ((lane >> 3) & 1) * 8;
    const int cA   = ((lane >> 4) & 1) * 8;
    const int rowB = (lane & 7) + ((lane >> 4) & 1) * 8;
    const int colB = ((lane >> 3) & 1) * 8;

    float acc[4][4][4];
#pragma unroll
    for (int i = 0; i < 4; i++)
#pragma unroll
        for (int j = 0; j < 4; j++)
#pragma unroll
            for (int q = 0; q < 4; q++) acc[i][j][q] = 0.0f;

    for (int ch = 0; ch < D_MODEL / GKC; ch++) {
        const int k0 = ch * GKC;
        __syncthreads();
#pragma unroll
        for (int p = 0; p < 4; p++) {
            int g  = tid + p * 256;         // 0..1023 = 128 rows x 8 uint4
            int r  = g >> 3;
            int c8 = (g & 7) * 8;
            int so = r * LDSR + c8;
            *(uint4*)(sAh + so) = *(const uint4*)(Ah + (size_t)(m0 + r) * D_MODEL + k0 + c8);
            *(uint4*)(sAl + so) = *(const uint4*)(Al + (size_t)(m0 + r) * D_MODEL + k0 + c8);
            *(uint4*)(sBh + so) = *(const uint4*)(Wh + (size_t)(n0 + r) * D_MODEL + k0 + c8);
            *(uint4*)(sBl + so) = *(const uint4*)(Wl + (size_t)(n0 + r) * D_MODEL + k0 + c8);
        }
        __syncthreads();

#pragma unroll
        for (int ks = 0; ks < 4; ks++) {
            uint32_t ah[4][4], al[4][4];
#pragma unroll
            for (int i = 0; i < 4; i++) {
                uint32_t off = (uint32_t)((rA + i * 16) * LDSR + ks * 16 + cA) * 2;
                ldsm_x4(ah[i], aAh + off);
                ldsm_x4(al[i], aAl + off);
            }
#pragma unroll
            for (int jp = 0; jp < 2; jp++) {
                uint32_t bh4[4], bl4[4];
                uint32_t off = (uint32_t)((wn * 32 + jp * 16 + rowB) * LDSR
                                          + ks * 16 + colB) * 2;
                ldsm_x4(bh4, aBh + off);
                ldsm_x4(bl4, aBl + off);
#pragma unroll
                for (int i = 0; i < 4; i++) {
                    mma16816(acc[i][2 * jp],     ah[i], bh4[0], bh4[1]);
                    mma16816(acc[i][2 * jp],     al[i], bh4[0], bh4[1]);
                    mma16816(acc[i][2 * jp],     ah[i], bl4[0], bl4[1]);
                    mma16816(acc[i][2 * jp + 1], ah[i], bh4[2], bh4[3]);
                    mma16816(acc[i][2 * jp + 1], al[i], bh4[2], bh4[3]);
                    mma16816(acc[i][2 * jp + 1], ah[i], bl4[2], bl4[3]);
                }
            }
        }
    }

#pragma unroll
    for (int i = 0; i < 4; i++) {
#pragma unroll
        for (int j = 0; j < 4; j++) {
            int R0 = m0 + wm * 64 + i * 16 + (lane >> 2);
            int C  = n0 + wn * 32 + j * 8 + (lane & 3) * 2;
            if (a_sel == 0) {
                int hh = C >> 6, d = C & 63;
#pragma unroll
                for (int half = 0; half < 2; half++) {
                    int R = R0 + half * 8;
                    int b = R >> 11, t = R & 2047;
                    size_t o = ((size_t)(b * N_HEADS + hh) * SEQ + t) * HEAD_DIM + d;
                    float v0 = acc[i][j][half * 2], v1 = acc[i][j][half * 2 + 1];
                    if (isV) {
                        uint32_t hi, lo;
                        split2(v0, v1, hi, lo);
                        *(uint32_t*)(g_Vh + o) = hi;
                        *(uint32_t*)(g_Vl + o) = lo;
                    } else {
                        *(float2*)(dstF + o) = make_float2(v0, v1);
                    }
                }
            } else {
#pragma unroll
                for (int half = 0; half < 2; half++) {
                    int R = R0 + half * 8;
                    *(float2*)(outPlain + (size_t)R * D_MODEL + C) =
                        make_float2(acc[i][j][half * 2], acc[i][j][half * 2 + 1]);
                }
            }
        }
    }
}

// ---------------- RoPE + bf16 hi/lo split (scale 1/8 folded into Q) --------
__global__ void __launch_bounds__(256)
rope_split_kernel()
{
    int idx = blockIdx.x * blockDim.x + threadIdx.x;   // B*H*T*32
    int d  = idx & 31;
    int t  = (idx >> 5) & (SEQ - 1);
    int bh = idx >> 16;

    float inv_freq = expf(-(float)d * 0.28782313662425573f);
    float ang = (float)t * inv_freq;
    float s, c;
    sincosf(ang, &s, &c);

    size_t base = ((size_t)bh * SEQ + t) * HEAD_DIM + d;
    float q1 = g_Q[base], q2 = g_Q[base + 32];
    float qa = (q1 * c - q2 * s) * 0.125f;
    float qb = (q2 * c + q1 * s) * 0.125f;
    float k1 = g_K[base], k2 = g_K[base + 32];
    float ka = k1 * c - k2 * s;
    float kb = k2 * c + k1 * s;

    __nv_bfloat16 h;
    h = __float2bfloat16_rn(qa); g_Qh[base] = h;      g_Ql[base]      = __float2bfloat16_rn(qa - __bfloat162float(h));
    h = __float2bfloat16_rn(qb); g_Qh[base + 32] = h; g_Ql[base + 32] = __float2bfloat16_rn(qb - __bfloat162float(h));
    h = __float2bfloat16_rn(ka); g_Kh[base] = h;      g_Kl[base]      = __float2bfloat16_rn(ka - __bfloat162float(h));
    h = __float2bfloat16_rn(kb); g_Kh[base + 32] = h; g_Kl[base + 32] = __float2bfloat16_rn(kb - __bfloat162float(h));
}

// ---------------- Flash attention (causal, HMMA bf16 split) -----------------
#define FLD 72

__global__ void __launch_bounds__(256, 2)
flash_mma_kernel()
{
    extern __shared__ __nv_bfloat16 sb[];
    __nv_bfloat16* sQh = sb;                 // [128][72]
    __nv_bfloat16* sQl = sb + 9216;
    __nv_bfloat16* sKh = sb + 18432;         // [64][72]
    __nv_bfloat16* sKl = sb + 23040;
    __nv_bfloat16* sVh = sb + 27648;
    __nv_bfloat16* sVl = sb + 32256;

    const int tid  = threadIdx.x;
    const int wid  = tid >> 5;
    const int lane = tid & 31;
    const int it   = (int)gridDim.x - 1 - (int)blockIdx.x;   // heavy first
    const int bh   = blockIdx.y;
    const size_t base = (size_t)bh * SEQ * HEAD_DIM;

    const uint32_t aQh = smem_u32(sQh);
    const uint32_t aQl = aQh + 18432;
    const uint32_t aKh = aQh + 36864;
    const uint32_t aKl = aQh + 46080;
    const uint32_t aVh = aQh + 55296;
    const uint32_t aVl = aQh + 64512;

    {
        const __nv_bfloat16* qh = g_Qh + base + (size_t)it * 128 * 64;
        const __nv_bfloat16* ql = g_Ql + base + (size_t)it * 128 * 64;
#pragma unroll
        for (int p = 0; p < 4; p++) {
            int g = tid + p * 256;
            int r = g >> 3, c8 = (g & 7) * 8;
            *(uint4*)(sQh + r * FLD + c8) = *(const uint4*)(qh + r * 64 + c8);
            *(uint4*)(sQl + r * FLD + c8) = *(const uint4*)(ql + r * 64 + c8);
        }
    }
    __syncthreads();

    uint32_t qh[4][4], ql[4][4];
    {
        int rAq = (lane & 7) + ((lane >> 3) & 1) * 8;
        int cAq = ((lane >> 4) & 1) * 8;
#pragma unroll
        for (int ks = 0; ks < 4; ks++) {
            uint32_t off = (uint32_t)((wid * 16 + rAq) * FLD + ks * 16 + cAq) * 2;
            ldsm_x4(qh[ks], aQh + off);
            ldsm_x4(ql[ks], aQl + off);
        }
    }

    float accO[8][4];
#pragma unroll
    for (int j = 0; j < 8; j++)
#pragma unroll
        for (int q = 0; q < 4; q++) accO[j][q] = 0.0f;
    float m0 = -1e30f, m1 = -1e30f, l0 = 0.0f, l1 = 0.0f;

    const int rowK = (lane & 7) + ((lane >> 4) & 1) * 8;
    const int colK = ((lane >> 3) & 1) * 8;
    const int rowV = (lane & 15);
    const int colV = (lane >> 4) * 8;

    const int jt_end = 2 * it + 1;
    for (int jt = 0; jt <= jt_end; jt++) {
        __syncthreads();
        {
            const size_t kb = base + (size_t)jt * 64 * 64;
#pragma unroll
            for (int p = 0; p < 2; p++) {
                int g = tid + p * 256;
                int r = g >> 3, c8 = (g & 7) * 8;
                *(uint4*)(sKh + r * FLD + c8) = *(const uint4*)(g_Kh + kb + r * 64 + c8);
                *(uint4*)(sKl + r * FLD + c8) = *(const uint4*)(g_Kl + kb + r * 64 + c8);
                *(uint4*)(sVh + r * FLD + c8) = *(const uint4*)(g_Vh + kb + r * 64 + c8);
                *(uint4*)(sVl + r * FLD + c8) = *(const uint4*)(g_Vl + kb + r * 64 + c8);
            }
        }
        __syncthreads();

        float s[8][4];
#pragma unroll
        for (int j = 0; j < 8; j++)
#pragma unroll
            for (int q = 0; q < 4; q++) s[j][q] = 0.0f;

#pragma unroll
        for (int ks = 0; ks < 4; ks++) {
#pragma unroll
            for (int pr = 0; pr < 4; pr++) {
                uint32_t kh4[4], kl4[4];
                uint32_t off = (uint32_t)((pr * 16 + rowK) * FLD + ks * 16 + colK) * 2;
                ldsm_x4(kh4, aKh + off);
                ldsm_x4(kl4, aKl + off);
                mma16816(s[2 * pr],     qh[ks], kh4[0], kh4[1]);
                mma16816(s[2 * pr],     ql[ks], kh4[0], kh4[1]);
                mma16816(s[2 * pr],     qh[ks], kl4[0], kl4[1]);
                mma16816(s[2 * pr + 1], qh[ks], kh4[2], kh4[3]);
                mma16816(s[2 * pr + 1], ql[ks], kh4[2], kh4[3]);
                mma16816(s[2 * pr + 1], qh[ks], kl4[2], kl4[3]);
            }
        }

        if (jt >= 2 * it) {
            int row0 = it * 128 + wid * 16 + (lane >> 2);
#pragma unroll
            for (int j = 0; j < 8; j++) {
                int col = jt * 64 + j * 8 + (lane & 3) * 2;
                if (col     > row0)     s[j][0] = -1e30f;
                if (col + 1 > row0)     s[j][1] = -1e30f;
                if (col     > row0 + 8) s[j][2] = -1e30f;
                if (col + 1 > row0 + 8) s[j][3] = -1e30f;
            }
        }

        float mx0 = -1e30f, mx1 = -1e30f;
#pragma unroll
        for (int j = 0; j < 8; j++) {
            mx0 = fmaxf(mx0, fmaxf(s[j][0], s[j][1]));
            mx1 = fmaxf(mx1, fmaxf(s[j][2], s[j][3]));
        }
        mx0 = fmaxf(mx0, __shfl_xor_sync(0xffffffffu, mx0, 1));
        mx0 = fmaxf(mx0, __shfl_xor_sync(0xffffffffu, mx0, 2));
        mx1 = fmaxf(mx1, __shfl_xor_sync(0xffffffffu, mx1, 1));
        mx1 = fmaxf(mx1, __shfl_xor_sync(0xffffffffu, mx1, 2));
        float m0n = fmaxf(m0, mx0), m1n = fmaxf(m1, mx1);
        float r0 = __expf(m0 - m0n);
        float r1 = __expf(m1 - m1n);
        m0 = m0n; m1 = m1n;
        float rs0 = 0.0f, rs1 = 0.0f;
#pragma unroll
        for (int j = 0; j < 8; j++) {
            s[j][0] = __expf(s[j][0] - m0n);
            s[j][1] = __expf(s[j][1] - m0n);
            s[j][2] = __expf(s[j][2] - m1n);
            s[j][3] = __expf(s[j][3] - m1n);
            rs0 += s[j][0] + s[j][1];
            rs1 += s[j][2] + s[j][3];
        }
        rs0 += __shfl_xor_sync(0xffffffffu, rs0, 1);
        rs0 += __shfl_xor_sync(0xffffffffu, rs0, 2);
        rs1 += __shfl_xor_sync(0xffffffffu, rs1, 1);
        rs1 += __shfl_xor_sync(0xffffffffu, rs1, 2);
        l0 = l0 * r0 + rs0;
        l1 = l1 * r1 + rs1;
#pragma unroll
        for (int j = 0; j < 8; j++) {
            accO[j][0] *= r0; accO[j][1] *= r0;
            accO[j][2] *= r1; accO[j][3] *= r1;
        }

#pragma unroll
        for (int ks = 0; ks < 4; ks++) {
            uint32_t ph[4], pl[4];
            split2(s[2 * ks][0],     s[2 * ks][1],     ph[0], pl[0]);
            split2(s[2 * ks][2],     s[2 * ks][3],     ph[1], pl[1]);
            split2(s[2 * ks + 1][0], s[2 * ks + 1][1], ph[2], pl[2]);
            split2(s[2 * ks + 1][2], s[2 * ks + 1][3], ph[3], pl[3]);
#pragma unroll
            for (int dp = 0; dp < 4; dp++) {
                uint32_t vh4[4], vl4[4];
                uint32_t off = (uint32_t)((ks * 16 + rowV) * FLD + dp * 16 + colV) * 2;
                ldsm_x4_t(vh4, aVh + off);
                ldsm_x4_t(vl4, aVl + off);
                mma16816(accO[2 * dp],     ph, vh4[0], vh4[1]);
                mma16816(accO[2 * dp],     pl, vh4[0], vh4[1]);
                mma16816(accO[2 * dp],     ph, vl4[0], vl4[1]);
                mma16816(accO[2 * dp + 1], ph, vh4[2], vh4[3]);
                mma16816(accO[2 * dp + 1], pl, vh4[2], vh4[3]);
                mma16816(accO[2 * dp + 1], ph, vl4[2], vl4[3]);
            }
        }
    }

    // ---- epilogue: O / l -> pre-split bf16 [B,T,D] ----
    float i0 = 1.0f / l0, i1 = 1.0f / l1;
    const int b = bh >> 4, hh = bh & 15;
    const int t0 = it * 128 + wid * 16 + (lane >> 2);
#pragma unroll
    for (int j = 0; j < 8; j++) {
        int d = hh * 64 + j * 8 + (lane & 3) * 2;
        size_t o0 = (size_t)(b * SEQ + t0) * D_MODEL + d;
        size_t o1 = (size_t)(b * SEQ + t0 + 8) * D_MODEL + d;
        uint32_t hi, lo;
        split2(accO[j][0] * i0, accO[j][1] * i0, hi, lo);
        *(uint32_t*)(g_Oh + o0) = hi;
        *(uint32_t*)(g_Ol + o0) = lo;
        split2(accO[j][2] * i1, accO[j][3] * i1, hi, lo);
        *(uint32_t*)(g_Oh + o1) = hi;
        *(uint32_t*)(g_Ol + o1) = lo;
    }
}

// ---------------- launch ----------------------------------------------------
extern "C" void kernel_launch(void* const* d_in, const int* in_sizes, int n_in,
                              void* d_out, int out_size)
{
    const float* x  = (const float*)d_in[0];
    const float* Wq = (const float*)d_in[1];
    const float* Wk = (const float*)d_in[2];
    const float* Wv = (const float*)d_in[3];
    const float* Wo = (const float*)d_in[4];
    float* out = (float*)d_out;

    cudaFuncSetAttribute(gemm_bf16_kernel,
                         cudaFuncAttributeMaxDynamicSharedMemorySize, GEMM_SMEM);
    cudaFuncSetAttribute(flash_mma_kernel,
                         cudaFuncAttributeMaxDynamicSharedMemorySize, 73728);

    // 0) pre-split inputs to bf16 hi/lo
    split_x_kernel<<<NELEM / 4 / 256, 256>>>(x);
    split_w_kernel<<<(4 * 1024 * 1024) / 4 / 256, 256>>>(Wq, Wk, Wv, Wo);

    // 1) fused QKV projections (grid.z selects weight slot)
    dim3 gq(D_MODEL / 128, M_ROWS / 128, 3);
    gemm_bf16_kernel<<<gq, 256, GEMM_SMEM>>>(0, nullptr);

    // 2) RoPE + hi/lo split on Q (scaled by 1/8) and K
    rope_split_kernel<<<(BATCH * N_HEADS * SEQ * 32) / 256, 256>>>();

    // 3) causal flash attention (HMMA) -> g_Oh/g_Ol
    flash_mma_kernel<<<dim3(SEQ / 128, BATCH * N_HEADS), 256, 73728>>>();

    // 4) output projection: out = O @ Wo^T
    dim3 go(D_MODEL / 128, M_ROWS / 128, 1);
    gemm_bf16_kernel<<<go, 256, GEMM_SMEM>>>(1, out);
}